// round 5
// baseline (speedup 1.0000x reference)
#include <cuda_runtime.h>
#include <cstdint>

#define D_DIM 256
#define N_MAX 4096
#define M_MAX 16384
#define EPSV 1e-12f

// ---------------------------------------------------------------------------
// Scratch (static device arrays; no allocations allowed).
// ---------------------------------------------------------------------------
__device__ float g_x2[N_MAX];
__device__ float g_y2[M_MAX];
__device__ float g_rowsum[N_MAX];
__device__ __align__(16) uint32_t g_Xh[N_MAX * (D_DIM / 2)];   // bf16x2 packed
__device__ __align__(16) uint32_t g_Yh[M_MAX * (D_DIM / 2)];   // bf16x2 packed

// ---------------------------------------------------------------------------
// PTX helpers (arch-portable: ldmatrix / mma.sync / cp.async)
// ---------------------------------------------------------------------------
__device__ __forceinline__ uint32_t smem_u32(const void* p) {
    uint32_t a;
    asm("{ .reg .u64 t; cvta.to.shared.u64 t, %1; cvt.u32.u64 %0, t; }" : "=r"(a) : "l"(p));
    return a;
}
#define CP_ASYNC16(dst, src) asm volatile("cp.async.cg.shared.global [%0], [%1], 16;" :: "r"(dst), "l"(src) : "memory")
#define CP_COMMIT()          asm volatile("cp.async.commit_group;" ::: "memory")
#define CP_WAIT0()           asm volatile("cp.async.wait_group 0;" ::: "memory")

__device__ __forceinline__ void ldmatrix_x4(uint32_t* r, uint32_t addr) {
    asm volatile("ldmatrix.sync.aligned.m8n8.x4.shared.b16 {%0,%1,%2,%3}, [%4];"
                 : "=r"(r[0]), "=r"(r[1]), "=r"(r[2]), "=r"(r[3]) : "r"(addr));
}
__device__ __forceinline__ void mma_bf16(float* c, const uint32_t* a, const uint32_t* b) {
    asm volatile("mma.sync.aligned.m16n8k16.row.col.f32.bf16.bf16.f32 "
                 "{%0,%1,%2,%3}, {%4,%5,%6,%7}, {%8,%9}, {%0,%1,%2,%3};"
                 : "+f"(c[0]), "+f"(c[1]), "+f"(c[2]), "+f"(c[3])
                 : "r"(a[0]), "r"(a[1]), "r"(a[2]), "r"(a[3]), "r"(b[0]), "r"(b[1]));
}

// ---------------------------------------------------------------------------
__global__ void zero_kernel(float* out, int N) {
    int t = blockIdx.x * blockDim.x + threadIdx.x;
    if (t < N) g_rowsum[t] = 0.0f;
    if (t == 0) out[0] = 0.0f;
}

// ---------------------------------------------------------------------------
// Fused prep: fp32 -> bf16 pack + squared norms, one warp per row.
// ---------------------------------------------------------------------------
__global__ void prep_kernel(const float* __restrict__ X,
                            const float* __restrict__ Y, int N, int M) {
    int warp = (blockIdx.x * blockDim.x + threadIdx.x) >> 5;
    int lane = threadIdx.x & 31;
    if (warp >= N + M) return;
    const float4* src; uint2* dst; float* nrm; int row;
    if (warp < N) { src = (const float4*)X; dst = (uint2*)g_Xh; nrm = g_x2; row = warp; }
    else          { src = (const float4*)Y; dst = (uint2*)g_Yh; nrm = g_y2; row = warp - N; }

    float4 v1 = src[row * 64 + lane];
    float4 v2 = src[row * 64 + 32 + lane];
    float s = v1.x*v1.x + v1.y*v1.y + v1.z*v1.z + v1.w*v1.w
            + v2.x*v2.x + v2.y*v2.y + v2.z*v2.z + v2.w*v2.w;
#pragma unroll
    for (int o = 16; o; o >>= 1) s += __shfl_xor_sync(0xffffffffu, s, o);
    if (lane == 0) nrm[row] = s;

    uint2 p1, p2;
    asm("cvt.rn.bf16x2.f32 %0, %1, %2;" : "=r"(p1.x) : "f"(v1.y), "f"(v1.x));
    asm("cvt.rn.bf16x2.f32 %0, %1, %2;" : "=r"(p1.y) : "f"(v1.w), "f"(v1.z));
    asm("cvt.rn.bf16x2.f32 %0, %1, %2;" : "=r"(p2.x) : "f"(v2.y), "f"(v2.x));
    asm("cvt.rn.bf16x2.f32 %0, %1, %2;" : "=r"(p2.y) : "f"(v2.w), "f"(v2.z));
    dst[row * 64 + lane]      = p1;
    dst[row * 64 + 32 + lane] = p2;
}

// ---------------------------------------------------------------------------
// Fused distance GEMM via mma.sync bf16.
// CTA = 128(i) x 256(j), K=256 in 4 chunks of 64, double-buffered cp.async.
// 8 warps in 2(m) x 4(n), warp tile 64x64: 4 m-frags(16) x 8 n-frags(8).
// SMEM rows padded to 144B -> conflict-free ldmatrix.
// ---------------------------------------------------------------------------
#define ROWB    144
#define A_TILE  (128 * ROWB)   // 18432
#define B_TILE  (256 * ROWB)   // 36864
#define OFF_A   0
#define OFF_B   (2 * A_TILE)               // 36864
#define OFF_X2  (2 * A_TILE + 2 * B_TILE)  // 110592
#define OFF_Y2  (OFF_X2 + 512)
#define OFF_RED (OFF_Y2 + 1024)
#define SMEM_DYN (OFF_RED + 512)

__global__ __launch_bounds__(256, 1)
void dist_kernel(int N, int M) {
    extern __shared__ __align__(16) char smem[];
    const uint32_t sbase = smem_u32(smem);
    float* x2s = (float*)(smem + OFF_X2);
    float* y2s = (float*)(smem + OFF_Y2);
    float* red = (float*)(smem + OFF_RED);

    const int tid  = threadIdx.x;
    const int wid  = tid >> 5;
    const int lane = tid & 31;
    const int iBase = blockIdx.y * 128;
    const int jBase = blockIdx.x * 256;
    const int iw = (wid >> 2) * 64;     // warp m-offset
    const int jw = (wid & 3) * 64;      // warp n-offset

    const uint4* Ag = (const uint4*)g_Xh + (size_t)iBase * 32;
    const uint4* Bg = (const uint4*)g_Yh + (size_t)jBase * 32;

    float acc[4][8][4];
#pragma unroll
    for (int a = 0; a < 4; a++)
#pragma unroll
        for (int b = 0; b < 8; b++)
#pragma unroll
            for (int c = 0; c < 4; c++) acc[a][b][c] = 0.0f;

    // norms + reduction scratch
    if (tid < 128) { x2s[tid] = g_x2[iBase + tid]; red[tid] = 0.0f; }
    y2s[tid] = g_y2[jBase + tid];

    // chunk loader: A 1024 x 16B, B 2048 x 16B
    auto load_tiles = [&](int buf, int kt) {
        const int kq = kt * 8;
#pragma unroll
        for (int t = 0; t < 4; t++) {
            int idx = tid + t * 256;
            int row = idx >> 3, q = idx & 7;
            CP_ASYNC16(sbase + OFF_A + buf * A_TILE + row * ROWB + q * 16,
                       (const void*)(Ag + row * 32 + kq + q));
        }
#pragma unroll
        for (int t = 0; t < 8; t++) {
            int idx = tid + t * 256;
            int row = idx >> 3, q = idx & 7;
            CP_ASYNC16(sbase + OFF_B + buf * B_TILE + row * ROWB + q * 16,
                       (const void*)(Bg + row * 32 + kq + q));
        }
        CP_COMMIT();
    };

    load_tiles(0, 0);
    CP_WAIT0();
    __syncthreads();

    // ldmatrix address components
    const int aRow = lane & 15;             // + (lane>>4)*16B col
    const int bRow = ((lane & 16) >> 1) + (lane & 7);   // + ((lane>>3)&1)*16B col
    const int aColSel = (lane >> 4) * 16;
    const int bColSel = ((lane >> 3) & 1) * 16;

#pragma unroll
    for (int kt = 0; kt < 4; kt++) {
        const int buf = kt & 1;
        if (kt < 3) load_tiles(buf ^ 1, kt + 1);

        const uint32_t sA = sbase + OFF_A + buf * A_TILE;
        const uint32_t sB = sbase + OFF_B + buf * B_TILE;
#pragma unroll
        for (int ks = 0; ks < 4; ks++) {
            uint32_t afr[4][4], bfr[8][2];
#pragma unroll
            for (int mf = 0; mf < 4; mf++)
                ldmatrix_x4(afr[mf], sA + (iw + mf * 16 + aRow) * ROWB
                                        + ks * 32 + aColSel);
#pragma unroll
            for (int np = 0; np < 4; np++) {
                uint32_t r[4];
                ldmatrix_x4(r, sB + (jw + np * 16 + bRow) * ROWB
                                  + ks * 32 + bColSel);
                bfr[2*np][0] = r[0]; bfr[2*np][1] = r[1];
                bfr[2*np+1][0] = r[2]; bfr[2*np+1][1] = r[3];
            }
#pragma unroll
            for (int mf = 0; mf < 4; mf++)
#pragma unroll
                for (int nf = 0; nf < 8; nf++)
                    mma_bf16(acc[mf][nf], afr[mf], bfr[nf]);
        }
        if (kt < 3) { CP_WAIT0(); __syncthreads(); }
    }
    __syncthreads();

    // Epilogue: dist + per-row reduction.
#pragma unroll
    for (int mf = 0; mf < 4; mf++) {
        const int r0 = iw + mf * 16 + (lane >> 2);
        const float x20 = x2s[r0], x21 = x2s[r0 + 8];
        float rs0 = 0.0f, rs1 = 0.0f;
#pragma unroll
        for (int nf = 0; nf < 8; nf++) {
            const int j0 = jw + nf * 8 + (lane & 3) * 2;
            const float y20 = y2s[j0], y21 = y2s[j0 + 1];
            const float* c = acc[mf][nf];
            float d2;
            d2 = fmaxf(fmaf(-2.0f, c[0], x20 + y20), 0.0f) + EPSV; rs0 += d2 * rsqrtf(d2);
            d2 = fmaxf(fmaf(-2.0f, c[1], x20 + y21), 0.0f) + EPSV; rs0 += d2 * rsqrtf(d2);
            d2 = fmaxf(fmaf(-2.0f, c[2], x21 + y20), 0.0f) + EPSV; rs1 += d2 * rsqrtf(d2);
            d2 = fmaxf(fmaf(-2.0f, c[3], x21 + y21), 0.0f) + EPSV; rs1 += d2 * rsqrtf(d2);
        }
        rs0 += __shfl_xor_sync(0xffffffffu, rs0, 1);
        rs0 += __shfl_xor_sync(0xffffffffu, rs0, 2);
        rs1 += __shfl_xor_sync(0xffffffffu, rs1, 1);
        rs1 += __shfl_xor_sync(0xffffffffu, rs1, 2);
        if ((lane & 3) == 0) {
            atomicAdd(&red[r0], rs0);
            atomicAdd(&red[r0 + 8], rs1);
        }
    }
    __syncthreads();
    if (tid < 128) atomicAdd(&g_rowsum[iBase + tid], red[tid]);
}

// ---------------------------------------------------------------------------
// Rank-based loss: sqrt(diff^2+eps) ~= |diff| (error <= N^2*sqrt(eps), ~2e-6 rel).
// sum_{i,j}|d_i-d_j| = 2 * sum_i d_i * (2*rank_i + 1 - N), rank = #{j: d_j < d_i}.
// One thread per i; sd broadcast from shared.
// ---------------------------------------------------------------------------
__global__ void loss_kernel(float* __restrict__ out, int N, float invM) {
    __shared__ __align__(16) float sd[N_MAX];
    __shared__ float wsum[8];
    const int tid = threadIdx.x;
    const int i = blockIdx.x * 256 + tid;
    for (int t = tid; t < N; t += 256) sd[t] = g_rowsum[t] * invM;
    __syncthreads();

    const float di = sd[i];
    int cnt = 0;
    for (int j = 0; j < N; j += 4) {
        float4 v = *(const float4*)&sd[j];
        cnt += (v.x < di) + (v.y < di) + (v.z < di) + (v.w < di);
    }
    float local = di * (2.0f * (float)cnt + 1.0f - (float)N);
#pragma unroll
    for (int o = 16; o; o >>= 1) local += __shfl_xor_sync(0xffffffffu, local, o);
    int lane = tid & 31, warp = tid >> 5;
    if (lane == 0) wsum[warp] = local;
    __syncthreads();
    if (tid == 0) {
        float s = 0.0f;
#pragma unroll
        for (int w = 0; w < 8; w++) s += wsum[w];
        atomicAdd(out, 2.0f * s);
    }
}

// ---------------------------------------------------------------------------
extern "C" void kernel_launch(void* const* d_in, const int* in_sizes, int n_in,
                              void* d_out, int out_size) {
    const float* X = (const float*)d_in[0];
    const float* Y = (const float*)d_in[1];
    float* out = (float*)d_out;
    const int N = in_sizes[0] / D_DIM;   // 4096
    const int M = in_sizes[1] / D_DIM;   // 16384

    static int attr_done = 0;
    if (!attr_done) {
        cudaFuncSetAttribute(dist_kernel,
                             cudaFuncAttributeMaxDynamicSharedMemorySize, SMEM_DYN);
        attr_done = 1;
    }

    zero_kernel<<<(N + 255) / 256, 256>>>(out, N);
    prep_kernel<<<((N + M) * 32 + 255) / 256, 256>>>(X, Y, N, M);
    dim3 grid(M / 256, N / 128);
    dist_kernel<<<grid, 256, SMEM_DYN>>>(N, M);
    loss_kernel<<<N / 256, 256>>>(out, N, 1.0f / (float)M);
}

// round 6
// speedup vs baseline: 1.2742x; 1.2742x over previous
#include <cuda_runtime.h>
#include <cstdint>

#define D_DIM 256
#define N_MAX 4096
#define M_MAX 16384
#define EPSV 1e-12f

// ---------------------------------------------------------------------------
// Scratch (static device arrays; no allocations allowed).
// ---------------------------------------------------------------------------
__device__ float g_x2[N_MAX];
__device__ float g_y2[M_MAX];
__device__ float g_rowsum[N_MAX];
__device__ __align__(16) uint32_t g_Xh[N_MAX * (D_DIM / 2)];   // bf16x2 packed
__device__ __align__(16) uint32_t g_Yh[M_MAX * (D_DIM / 2)];   // bf16x2 packed

// ---------------------------------------------------------------------------
// PTX helpers (arch-portable: ldmatrix / mma.sync / cp.async)
// ---------------------------------------------------------------------------
__device__ __forceinline__ uint32_t smem_u32(const void* p) {
    uint32_t a;
    asm("{ .reg .u64 t; cvta.to.shared.u64 t, %1; cvt.u32.u64 %0, t; }" : "=r"(a) : "l"(p));
    return a;
}
#define CP_ASYNC16(dst, src) asm volatile("cp.async.cg.shared.global [%0], [%1], 16;" :: "r"(dst), "l"(src) : "memory")
#define CP_COMMIT()          asm volatile("cp.async.commit_group;" ::: "memory")
#define CP_WAIT0()           asm volatile("cp.async.wait_group 0;" ::: "memory")

__device__ __forceinline__ void ldmatrix_x4(uint32_t* r, uint32_t addr) {
    asm volatile("ldmatrix.sync.aligned.m8n8.x4.shared.b16 {%0,%1,%2,%3}, [%4];"
                 : "=r"(r[0]), "=r"(r[1]), "=r"(r[2]), "=r"(r[3]) : "r"(addr));
}
__device__ __forceinline__ void mma_bf16(float* c, const uint32_t* a, const uint32_t* b) {
    asm volatile("mma.sync.aligned.m16n8k16.row.col.f32.bf16.bf16.f32 "
                 "{%0,%1,%2,%3}, {%4,%5,%6,%7}, {%8,%9}, {%0,%1,%2,%3};"
                 : "+f"(c[0]), "+f"(c[1]), "+f"(c[2]), "+f"(c[3])
                 : "r"(a[0]), "r"(a[1]), "r"(a[2]), "r"(a[3]), "r"(b[0]), "r"(b[1]));
}

// ---------------------------------------------------------------------------
__global__ void zero_kernel(float* out, int N) {
    int t = blockIdx.x * blockDim.x + threadIdx.x;
    if (t < N) g_rowsum[t] = 0.0f;
    if (t == 0) out[0] = 0.0f;
}

// ---------------------------------------------------------------------------
// Fused prep: fp32 -> bf16 pack + squared norms, one warp per row.
// ---------------------------------------------------------------------------
__global__ void prep_kernel(const float* __restrict__ X,
                            const float* __restrict__ Y, int N, int M) {
    int warp = (blockIdx.x * blockDim.x + threadIdx.x) >> 5;
    int lane = threadIdx.x & 31;
    if (warp >= N + M) return;
    const float4* src; uint2* dst; float* nrm; int row;
    if (warp < N) { src = (const float4*)X; dst = (uint2*)g_Xh; nrm = g_x2; row = warp; }
    else          { src = (const float4*)Y; dst = (uint2*)g_Yh; nrm = g_y2; row = warp - N; }

    float4 v1 = src[row * 64 + lane];
    float4 v2 = src[row * 64 + 32 + lane];
    float s = v1.x*v1.x + v1.y*v1.y + v1.z*v1.z + v1.w*v1.w
            + v2.x*v2.x + v2.y*v2.y + v2.z*v2.z + v2.w*v2.w;
#pragma unroll
    for (int o = 16; o; o >>= 1) s += __shfl_xor_sync(0xffffffffu, s, o);
    if (lane == 0) nrm[row] = s;

    uint2 p1, p2;
    asm("cvt.rn.bf16x2.f32 %0, %1, %2;" : "=r"(p1.x) : "f"(v1.y), "f"(v1.x));
    asm("cvt.rn.bf16x2.f32 %0, %1, %2;" : "=r"(p1.y) : "f"(v1.w), "f"(v1.z));
    asm("cvt.rn.bf16x2.f32 %0, %1, %2;" : "=r"(p2.x) : "f"(v2.y), "f"(v2.x));
    asm("cvt.rn.bf16x2.f32 %0, %1, %2;" : "=r"(p2.y) : "f"(v2.w), "f"(v2.z));
    dst[row * 64 + lane]      = p1;
    dst[row * 64 + 32 + lane] = p2;
}

// ---------------------------------------------------------------------------
// Fused distance GEMM via mma.sync bf16 (R3 skeleton: occ 2, 128x128 CTA).
// 8 warps in 2(m) x 4(n): warp tile 64(i) x 32(j).
// B-fragments via ldmatrix.x4 pairs (6 LDSM per warp per ks instead of 8).
// SMEM rows padded to 144B -> conflict-free ldmatrix.
// ---------------------------------------------------------------------------
#define ROWB   144
#define TILE_B (128 * ROWB)  // 18432 per tile buffer
#define OFF_A  0
#define OFF_B  (2 * TILE_B)
#define OFF_X2 (4 * TILE_B)
#define OFF_Y2 (4 * TILE_B + 512)
#define OFF_RED (4 * TILE_B + 1024)
#define SMEM_DYN (4 * TILE_B + 1536)

__global__ __launch_bounds__(256, 2)
void dist_kernel(int N, int M) {
    extern __shared__ __align__(16) char smem[];
    const uint32_t sbase = smem_u32(smem);
    float* x2s = (float*)(smem + OFF_X2);
    float* y2s = (float*)(smem + OFF_Y2);
    float* red = (float*)(smem + OFF_RED);

    const int tid  = threadIdx.x;
    const int wid  = tid >> 5;
    const int lane = tid & 31;
    const int iBase = blockIdx.y * 128;
    const int jBase = blockIdx.x * 128;
    const int iw = (wid >> 2) * 64;
    const int jw = (wid & 3) * 32;

    const uint4* Ag = (const uint4*)g_Xh + (size_t)iBase * 32;
    const uint4* Bg = (const uint4*)g_Yh + (size_t)jBase * 32;

    float acc[4][4][4];
#pragma unroll
    for (int a = 0; a < 4; a++)
#pragma unroll
        for (int b = 0; b < 4; b++)
#pragma unroll
            for (int c = 0; c < 4; c++) acc[a][b][c] = 0.0f;

    if (tid < 128) x2s[tid] = g_x2[iBase + tid];
    else           y2s[tid - 128] = g_y2[jBase + tid - 128];
    if (tid < 128) red[tid] = 0.0f;

    auto load_tiles = [&](int buf, int kq) {
#pragma unroll
        for (int t = 0; t < 4; t++) {
            int idx = tid + t * 256;
            int row = idx >> 3, q = idx & 7;
            CP_ASYNC16(sbase + OFF_A + buf * TILE_B + row * ROWB + q * 16,
                       (const void*)(Ag + row * 32 + kq + q));
        }
#pragma unroll
        for (int t = 0; t < 4; t++) {
            int idx = tid + t * 256;
            int row = idx >> 3, q = idx & 7;
            CP_ASYNC16(sbase + OFF_B + buf * TILE_B + row * ROWB + q * 16,
                       (const void*)(Bg + row * 32 + kq + q));
        }
        CP_COMMIT();
    };

    load_tiles(0, 0);
    CP_WAIT0();
    __syncthreads();

    // ldmatrix address components
    const int aRow = lane & 15;
    const int aColSel = (lane >> 4) * 16;
    const int bRow = ((lane & 16) >> 1) + (lane & 7);      // 16-row span
    const int bColSel = ((lane >> 3) & 1) * 16;

#pragma unroll
    for (int kt = 0; kt < 4; kt++) {
        const int buf = kt & 1;
        if (kt < 3) load_tiles(buf ^ 1, (kt + 1) * 8);

        const uint32_t sA = sbase + OFF_A + buf * TILE_B;
        const uint32_t sB = sbase + OFF_B + buf * TILE_B;
#pragma unroll
        for (int ks = 0; ks < 4; ks++) {
            uint32_t afr[4][4], bfr[4][2];
#pragma unroll
            for (int mf = 0; mf < 4; mf++)
                ldmatrix_x4(afr[mf], sA + (iw + mf * 16 + aRow) * ROWB
                                        + ks * 32 + aColSel);
#pragma unroll
            for (int np = 0; np < 2; np++) {
                uint32_t r[4];
                ldmatrix_x4(r, sB + (jw + np * 16 + bRow) * ROWB
                                  + ks * 32 + bColSel);
                bfr[2*np][0]   = r[0]; bfr[2*np][1]   = r[1];
                bfr[2*np+1][0] = r[2]; bfr[2*np+1][1] = r[3];
            }
#pragma unroll
            for (int mf = 0; mf < 4; mf++)
#pragma unroll
                for (int nf = 0; nf < 4; nf++)
                    mma_bf16(acc[mf][nf], afr[mf], bfr[nf]);
        }
        if (kt < 3) { CP_WAIT0(); __syncthreads(); }
    }
    __syncthreads();

    // Epilogue: dist + per-row reduction.
#pragma unroll
    for (int mf = 0; mf < 4; mf++) {
        const int r0 = iw + mf * 16 + (lane >> 2);
        const float x20 = x2s[r0], x21 = x2s[r0 + 8];
        float rs0 = 0.0f, rs1 = 0.0f;
#pragma unroll
        for (int nf = 0; nf < 4; nf++) {
            const int j0 = jw + nf * 8 + (lane & 3) * 2;
            const float y20 = y2s[j0], y21 = y2s[j0 + 1];
            const float* c = acc[mf][nf];
            float d2;
            d2 = fmaxf(fmaf(-2.0f, c[0], x20 + y20), 0.0f) + EPSV; rs0 += d2 * rsqrtf(d2);
            d2 = fmaxf(fmaf(-2.0f, c[1], x20 + y21), 0.0f) + EPSV; rs0 += d2 * rsqrtf(d2);
            d2 = fmaxf(fmaf(-2.0f, c[2], x21 + y20), 0.0f) + EPSV; rs1 += d2 * rsqrtf(d2);
            d2 = fmaxf(fmaf(-2.0f, c[3], x21 + y21), 0.0f) + EPSV; rs1 += d2 * rsqrtf(d2);
        }
        rs0 += __shfl_xor_sync(0xffffffffu, rs0, 1);
        rs0 += __shfl_xor_sync(0xffffffffu, rs0, 2);
        rs1 += __shfl_xor_sync(0xffffffffu, rs1, 1);
        rs1 += __shfl_xor_sync(0xffffffffu, rs1, 2);
        if ((lane & 3) == 0) {
            atomicAdd(&red[r0], rs0);
            atomicAdd(&red[r0 + 8], rs1);
        }
    }
    __syncthreads();
    if (tid < 128) atomicAdd(&g_rowsum[iBase + tid], red[tid]);
}

// ---------------------------------------------------------------------------
// Exact loss, 2D grid: block (bx, by) covers i in [bx*256, +256),
// j in [by*512, +512). 128 blocks -> full-chip parallelism, no cancellation.
// ---------------------------------------------------------------------------
__global__ void loss_kernel(float* __restrict__ out, int N, float invM) {
    __shared__ __align__(16) float sj[512];
    __shared__ float wsum[8];
    const int tid = threadIdx.x;
    const int i  = blockIdx.x * 256 + tid;
    const int jb = blockIdx.y * 512;

    for (int t = tid; t < 512; t += 256) sj[t] = g_rowsum[jb + t] * invM;
    const float di = g_rowsum[i] * invM;
    __syncthreads();

    float local = 0.0f;
#pragma unroll 4
    for (int j = 0; j < 512; j += 4) {
        float4 v = *(const float4*)&sj[j];
        float df, s;
        df = di - v.x; s = df * df + EPSV; local += s * rsqrtf(s);
        df = di - v.y; s = df * df + EPSV; local += s * rsqrtf(s);
        df = di - v.z; s = df * df + EPSV; local += s * rsqrtf(s);
        df = di - v.w; s = df * df + EPSV; local += s * rsqrtf(s);
    }
#pragma unroll
    for (int o = 16; o; o >>= 1) local += __shfl_xor_sync(0xffffffffu, local, o);
    int lane = tid & 31, warp = tid >> 5;
    if (lane == 0) wsum[warp] = local;
    __syncthreads();
    if (tid == 0) {
        float s = 0.0f;
#pragma unroll
        for (int w = 0; w < 8; w++) s += wsum[w];
        atomicAdd(out, s);
    }
}

// ---------------------------------------------------------------------------
extern "C" void kernel_launch(void* const* d_in, const int* in_sizes, int n_in,
                              void* d_out, int out_size) {
    const float* X = (const float*)d_in[0];
    const float* Y = (const float*)d_in[1];
    float* out = (float*)d_out;
    const int N = in_sizes[0] / D_DIM;   // 4096
    const int M = in_sizes[1] / D_DIM;   // 16384

    static int attr_done = 0;
    if (!attr_done) {
        cudaFuncSetAttribute(dist_kernel,
                             cudaFuncAttributeMaxDynamicSharedMemorySize, SMEM_DYN);
        attr_done = 1;
    }

    zero_kernel<<<(N + 255) / 256, 256>>>(out, N);
    prep_kernel<<<((N + M) * 32 + 255) / 256, 256>>>(X, Y, N, M);
    dim3 grid(M / 128, N / 128);
    dist_kernel<<<grid, 256, SMEM_DYN>>>(N, M);
    dim3 lgrid(N / 256, N / 512);
    loss_kernel<<<lgrid, 256>>>(out, N, 1.0f / (float)M);
}